// round 5
// baseline (speedup 1.0000x reference)
#include <cuda_runtime.h>
#include <cuda_bf16.h>

// SoftPerspectiveShader: fused sample_textures + softmax_rgb_blend
// R4: revert fcol speculative prefetch (R2 regression: regs 48->56 cost a
// block of occupancy). Keep only the 3-register bary[k0] prefetch. Slim the
// math: __expf + __fdividef replace ~200 instructions/thread of accurate
// expf + fp32 divides that were competing with memory for issue slots.
// z_inv keeps the true division (its rounding is amplified x1e4 in the
// softmax exponent); everything else has O(2^-22) error vs 1e-3 tolerance.

#define SIGMA_INV 1e4f
#define GAMMA_INV 1e4f
#define ZFAR_F    100.0f
#define ZRANGE_F  99.0f
#define EPS_F     1e-10f

__global__ __launch_bounds__(256) void soft_shader_kernel(
    const int4*   __restrict__ p2f,    // [P][2] int4  (K=8)
    const float*  __restrict__ bary,   // [P][8][3]
    const float4* __restrict__ zbuf,   // [P][2] float4
    const float4* __restrict__ dists,  // [P][2] float4
    const float*  __restrict__ fcol,   // [F][3][3]
    float4*       __restrict__ out,    // [P]
    int P)
{
    int p = blockIdx.x * blockDim.x + threadIdx.x;
    if (p >= P) return;

    // ---- faces first: the select + bary prefetch hang off this ----
    const int4 fa = p2f[2 * p], fb = p2f[2 * p + 1];
    int faces[8] = {fa.x, fa.y, fa.z, fa.w, fb.x, fb.y, fb.z, fb.w};

    // first-valid fragment (argmax of masked z_inv since zbuf sorted asc)
    int  k0   = 7;
    bool hasv = faces[7] >= 0;
#pragma unroll
    for (int k = 6; k >= 0; k--) {
        bool v = faces[k] >= 0;
        k0   = v ? k : k0;
        hasv = hasv || v;
    }

    // ---- early bary prefetch for k0 (3 regs; DRAM-latency gather) ----
    const float* bc0 = bary + (size_t)p * 24 + (size_t)k0 * 3;
    float pb0 = __ldg(bc0 + 0), pb1 = __ldg(bc0 + 1), pb2 = __ldg(bc0 + 2);

    // ---- bulk loads ----
    const float4 za = zbuf[2 * p],  zb = zbuf[2 * p + 1];
    const float4 da = dists[2 * p], db = dists[2 * p + 1];
    float zv[8] = {za.x, za.y, za.z, za.w, zb.x, zb.y, zb.z, zb.w};
    float dv[8] = {da.x, da.y, da.z, da.w, db.x, db.y, db.z, db.w};

    // z_inv_max = z_inv of the first valid fragment (true div, matches ref)
    float zsel = 0.0f;
#pragma unroll
    for (int k = 7; k >= 0; k--) zsel = (faces[k] >= 0) ? zv[k] : zsel;
    float zinv_k0 = (ZFAR_F - zsel) / ZRANGE_F;
    float zmax = hasv ? fmaxf(zinv_k0, EPS_F) : EPS_F;

    float delta = fmaxf(__expf((EPS_F - zmax) * GAMMA_INV), EPS_F);
    float denom = delta;
    float keep  = 1.0f;
    float r = 0.0f, g = 0.0f, b = 0.0f;

#pragma unroll
    for (int k = 0; k < 8; k++) {
        bool  m  = faces[k] >= 0;
        // sigmoid(-d/sigma) = 1/(1+exp(d/sigma))
        float e  = __expf(dv[k] * SIGMA_INV);
        float pr = m ? __fdividef(1.0f, 1.0f + e) : 0.0f;
        keep *= (1.0f - pr);
        float zi = m ? ((ZFAR_F - zv[k]) / ZRANGE_F) : 0.0f;
        float w  = pr * __expf((zi - zmax) * GAMMA_INV);  // zi==zmax at k0 -> exp(0)=1
        denom += w;

        if (k == k0) {
            // dominant fragment: prefetched bary, inline fcol gather (L2-hot)
            const float* fc = fcol + (size_t)(faces[k] >= 0 ? faces[k] : 0) * 9;
            float t0 = pb0 * fc[0] + pb1 * fc[3] + pb2 * fc[6];
            float t1 = pb0 * fc[1] + pb1 * fc[4] + pb2 * fc[7];
            float t2 = pb0 * fc[2] + pb1 * fc[5] + pb2 * fc[8];
            float wm = hasv ? w : 0.0f;
            r += wm * t0; g += wm * t1; b += wm * t2;
        } else if (w > 0.0f) {
            // rare (~8%): second fragment within ~88*GAMMA of zmax
            const float* bc = bary + (size_t)p * 24 + (size_t)k * 3;
            float b0 = bc[0], b1 = bc[1], b2 = bc[2];
            const float* fc = fcol + (size_t)faces[k] * 9;
            float t0 = b0 * fc[0] + b1 * fc[3] + b2 * fc[6];
            float t1 = b0 * fc[1] + b1 * fc[4] + b2 * fc[7];
            float t2 = b0 * fc[2] + b1 * fc[5] + b2 * fc[8];
            r += w * t0; g += w * t1; b += w * t2;
        }
    }

    float inv = __fdividef(1.0f, denom);
    float4 o;
    o.x = (r + delta) * inv;   // background = (1,1,1)
    o.y = (g + delta) * inv;
    o.z = (b + delta) * inv;
    o.w = keep;                // 1 - alpha
    out[p] = o;
}

extern "C" void kernel_launch(void* const* d_in, const int* in_sizes, int n_in,
                              void* d_out, int out_size) {
    const int*   p2f   = (const int*)d_in[0];
    const float* bary  = (const float*)d_in[1];
    const float* zbufp = (const float*)d_in[2];
    const float* dist  = (const float*)d_in[3];
    const float* fcol  = (const float*)d_in[4];
    int P = in_sizes[0] / 8;   // N*H*W pixels

    int threads = 256;
    int blocks  = (P + threads - 1) / threads;
    soft_shader_kernel<<<blocks, threads>>>(
        (const int4*)p2f, bary, (const float4*)zbufp, (const float4*)dist,
        fcol, (float4*)d_out, P);
}

// round 6
// speedup vs baseline: 1.0090x; 1.0090x over previous
#include <cuda_runtime.h>
#include <cuda_bf16.h>

// SoftPerspectiveShader: fused sample_textures + softmax_rgb_blend
// R5: restore R1's load ordering. Post-mortem of R2/R4: placing the
// k0-dependent bary prefetch before the zbuf/dists loads dropped MLP_p1
// from 6 to 2 (warp stalled ~577cyc on p2f before issuing the other
// streaming loads) — DRAM-busy time was identical (28.1us) across R1/R4,
// all regression was idle gaps. Now: all 6 streaming LDG.128 issue first,
// THEN the select chain + bary[k0] prefetch (overlapping the slim weight
// math from R4). exp underflow at GAMMA=1e-4 still makes the softmax
// one-hot at the first valid fragment 92%+ of the time; w==0 fragments
// contribute exactly nothing, so their bary/fcol loads are skipped.

#define SIGMA_INV 1e4f
#define GAMMA_INV 1e4f
#define ZFAR_F    100.0f
#define ZRANGE_F  99.0f
#define EPS_F     1e-10f

__global__ __launch_bounds__(256) void soft_shader_kernel(
    const int4*   __restrict__ p2f,    // [P][2] int4  (K=8)
    const float*  __restrict__ bary,   // [P][8][3]
    const float4* __restrict__ zbuf,   // [P][2] float4
    const float4* __restrict__ dists,  // [P][2] float4
    const float*  __restrict__ fcol,   // [F][3][3]
    float4*       __restrict__ out,    // [P]
    int P)
{
    int p = blockIdx.x * blockDim.x + threadIdx.x;
    if (p >= P) return;

    // ---- ALL six streaming loads issue back-to-back (MLP_p1 = 6) ----
    const int4   fa = p2f[2 * p],   fb = p2f[2 * p + 1];
    const float4 za = zbuf[2 * p],  zb = zbuf[2 * p + 1];
    const float4 da = dists[2 * p], db = dists[2 * p + 1];

    int   faces[8] = {fa.x, fa.y, fa.z, fa.w, fb.x, fb.y, fb.z, fb.w};
    float zv[8]    = {za.x, za.y, za.z, za.w, zb.x, zb.y, zb.z, zb.w};
    float dv[8]    = {da.x, da.y, da.z, da.w, db.x, db.y, db.z, db.w};

    // first-valid fragment = argmax of masked z_inv (zbuf sorted ascending)
    int  k0   = 7;
    bool hasv = faces[7] >= 0;
#pragma unroll
    for (int k = 6; k >= 0; k--) {
        bool v = faces[k] >= 0;
        k0   = v ? k : k0;
        hasv = hasv || v;
    }

    // bary[k0] prefetch: issues as soon as p2f lands, overlaps weight math
    const float* bc0 = bary + (size_t)p * 24 + (size_t)k0 * 3;
    float pb0 = bc0[0], pb1 = bc0[1], pb2 = bc0[2];

    // z_inv_max = z_inv of first valid fragment (true div, matches reference)
    float zsel = 0.0f;
#pragma unroll
    for (int k = 7; k >= 0; k--) zsel = (faces[k] >= 0) ? zv[k] : zsel;
    float zinv_k0 = (ZFAR_F - zsel) / ZRANGE_F;
    float zmax = hasv ? fmaxf(zinv_k0, EPS_F) : EPS_F;

    float delta = fmaxf(__expf((EPS_F - zmax) * GAMMA_INV), EPS_F);
    float denom = delta;
    float keep  = 1.0f;
    float r = 0.0f, g = 0.0f, b = 0.0f;

#pragma unroll
    for (int k = 0; k < 8; k++) {
        bool  m  = faces[k] >= 0;
        // sigmoid(-d/sigma) = 1/(1+exp(d/sigma))
        float e  = __expf(dv[k] * SIGMA_INV);
        float pr = m ? __fdividef(1.0f, 1.0f + e) : 0.0f;
        keep *= (1.0f - pr);
        float zi = m ? ((ZFAR_F - zv[k]) / ZRANGE_F) : 0.0f;
        float w  = pr * __expf((zi - zmax) * GAMMA_INV);  // exp(0)=1 at k0
        denom += w;

        if (k == k0) {
            // dominant fragment: prefetched bary, fcol gather (L2-hot 7.2MB)
            const float* fc = fcol + (size_t)(faces[k] >= 0 ? faces[k] : 0) * 9;
            float t0 = pb0 * fc[0] + pb1 * fc[3] + pb2 * fc[6];
            float t1 = pb0 * fc[1] + pb1 * fc[4] + pb2 * fc[7];
            float t2 = pb0 * fc[2] + pb1 * fc[5] + pb2 * fc[8];
            float wm = hasv ? w : 0.0f;
            r += wm * t0; g += wm * t1; b += wm * t2;
        } else if (w > 0.0f) {
            // rare: another fragment within ~88*GAMMA of zmax
            const float* bc = bary + (size_t)p * 24 + (size_t)k * 3;
            float b0 = bc[0], b1 = bc[1], b2 = bc[2];
            const float* fc = fcol + (size_t)faces[k] * 9;
            float t0 = b0 * fc[0] + b1 * fc[3] + b2 * fc[6];
            float t1 = b0 * fc[1] + b1 * fc[4] + b2 * fc[7];
            float t2 = b0 * fc[2] + b1 * fc[5] + b2 * fc[8];
            r += w * t0; g += w * t1; b += w * t2;
        }
    }

    float inv = __fdividef(1.0f, denom);
    float4 o;
    o.x = (r + delta) * inv;   // background = (1,1,1)
    o.y = (g + delta) * inv;
    o.z = (b + delta) * inv;
    o.w = keep;                // 1 - alpha
    out[p] = o;
}

extern "C" void kernel_launch(void* const* d_in, const int* in_sizes, int n_in,
                              void* d_out, int out_size) {
    const int*   p2f   = (const int*)d_in[0];
    const float* bary  = (const float*)d_in[1];
    const float* zbufp = (const float*)d_in[2];
    const float* dist  = (const float*)d_in[3];
    const float* fcol  = (const float*)d_in[4];
    int P = in_sizes[0] / 8;   // N*H*W pixels

    int threads = 256;
    int blocks  = (P + threads - 1) / threads;
    soft_shader_kernel<<<blocks, threads>>>(
        (const int4*)p2f, bary, (const float4*)zbufp, (const float4*)dist,
        fcol, (float4*)d_out, P);
}

// round 7
// speedup vs baseline: 1.0148x; 1.0058x over previous
#include <cuda_runtime.h>
#include <cuda_bf16.h>

// SoftPerspectiveShader: fused sample_textures + softmax_rgb_blend
// R6: attack L1tex wavefront amplification. DRAM-busy time is pinned at
// ~28us in every prior variant; all loss is latency/queue gaps. The fcol
// gather (9 divergent scalar LDGs ~ 288 wavefronts/warp) dominated the L1
// queue. Fix: pre-pad face_colors 36B->48B rows in a tiny first kernel so
// the gather is 3x LDG.128; vectorize the bary[k0] read (16B-aligned when
// k0==0, which holds for 99.9995% of pixels).

#define SIGMA_INV 1e4f
#define GAMMA_INV 1e4f
#define ZFAR_F    100.0f
#define ZRANGE_F  99.0f
#define EPS_F     1e-10f
#define MAX_F     200000

// padded face colors: [F][3] float4 (vertex-major, w unused) = 9.6MB
__device__ float4 g_fcol_pad[MAX_F * 3];

__global__ __launch_bounds__(256) void pad_fcol_kernel(
    const float* __restrict__ fcol, int F)
{
    int f = blockIdx.x * blockDim.x + threadIdx.x;
    if (f >= F) return;
    const float* s = fcol + (size_t)f * 9;   // coalesced-ish consecutive reads
    float4 v0 = make_float4(s[0], s[1], s[2], 0.0f);
    float4 v1 = make_float4(s[3], s[4], s[5], 0.0f);
    float4 v2 = make_float4(s[6], s[7], s[8], 0.0f);
    g_fcol_pad[3 * f + 0] = v0;
    g_fcol_pad[3 * f + 1] = v1;
    g_fcol_pad[3 * f + 2] = v2;
}

__global__ __launch_bounds__(256) void soft_shader_kernel(
    const int4*   __restrict__ p2f,    // [P][2] int4  (K=8)
    const float*  __restrict__ bary,   // [P][8][3]
    const float4* __restrict__ zbuf,   // [P][2] float4
    const float4* __restrict__ dists,  // [P][2] float4
    float4*       __restrict__ out,    // [P]
    int P)
{
    int p = blockIdx.x * blockDim.x + threadIdx.x;
    if (p >= P) return;

    // ---- all six streaming LDG.128 issue back-to-back (MLP_p1 = 6) ----
    const int4   fa = p2f[2 * p],   fb = p2f[2 * p + 1];
    const float4 za = zbuf[2 * p],  zb = zbuf[2 * p + 1];
    const float4 da = dists[2 * p], db = dists[2 * p + 1];

    int   faces[8] = {fa.x, fa.y, fa.z, fa.w, fb.x, fb.y, fb.z, fb.w};
    float zv[8]    = {za.x, za.y, za.z, za.w, zb.x, zb.y, zb.z, zb.w};
    float dv[8]    = {da.x, da.y, da.z, da.w, db.x, db.y, db.z, db.w};

    // first-valid fragment = argmax of masked z_inv (zbuf sorted ascending)
    int  k0   = 7;
    bool hasv = faces[7] >= 0;
#pragma unroll
    for (int k = 6; k >= 0; k--) {
        bool v = faces[k] >= 0;
        k0   = v ? k : k0;
        hasv = hasv || v;
    }
    int f0 = 0;
#pragma unroll
    for (int k = 7; k >= 0; k--) f0 = (faces[k] >= 0) ? faces[k] : f0;

    // ---- bary[k0]: vector fast path (k0==0 => 16B-aligned at p*96) ----
    float pb0, pb1, pb2;
    if (k0 == 0) {
        float4 bv = *(const float4*)(bary + (size_t)p * 24);
        pb0 = bv.x; pb1 = bv.y; pb2 = bv.z;
    } else {
        const float* bc0 = bary + (size_t)p * 24 + (size_t)k0 * 3;
        pb0 = bc0[0]; pb1 = bc0[1]; pb2 = bc0[2];
    }

    // ---- padded fcol gather for dominant fragment: 3 x LDG.128 ----
    float4 v0 = g_fcol_pad[3 * f0 + 0];
    float4 v1 = g_fcol_pad[3 * f0 + 1];
    float4 v2 = g_fcol_pad[3 * f0 + 2];

    // z_inv_max = z_inv of first valid fragment (true div, matches reference)
    float zsel = 0.0f;
#pragma unroll
    for (int k = 7; k >= 0; k--) zsel = (faces[k] >= 0) ? zv[k] : zsel;
    float zinv_k0 = (ZFAR_F - zsel) / ZRANGE_F;
    float zmax = hasv ? fmaxf(zinv_k0, EPS_F) : EPS_F;

    float delta = fmaxf(__expf((EPS_F - zmax) * GAMMA_INV), EPS_F);
    float denom = delta;
    float keep  = 1.0f;
    float r = 0.0f, g = 0.0f, b = 0.0f;

#pragma unroll
    for (int k = 0; k < 8; k++) {
        bool  m  = faces[k] >= 0;
        // sigmoid(-d/sigma) = 1/(1+exp(d/sigma))
        float e  = __expf(dv[k] * SIGMA_INV);
        float pr = m ? __fdividef(1.0f, 1.0f + e) : 0.0f;
        keep *= (1.0f - pr);
        float zi = m ? ((ZFAR_F - zv[k]) / ZRANGE_F) : 0.0f;
        float w  = pr * __expf((zi - zmax) * GAMMA_INV);  // exp(0)=1 at k0
        denom += w;

        if (k == k0) {
            float t0 = pb0 * v0.x + pb1 * v1.x + pb2 * v2.x;
            float t1 = pb0 * v0.y + pb1 * v1.y + pb2 * v2.y;
            float t2 = pb0 * v0.z + pb1 * v1.z + pb2 * v2.z;
            float wm = hasv ? w : 0.0f;
            r += wm * t0; g += wm * t1; b += wm * t2;
        } else if (w > 0.0f) {
            // rare (~7%/pixel): another fragment within ~88*GAMMA of zmax
            const float* bc = bary + (size_t)p * 24 + (size_t)k * 3;
            float b0 = bc[0], b1 = bc[1], b2 = bc[2];
            float4 u0 = g_fcol_pad[3 * faces[k] + 0];
            float4 u1 = g_fcol_pad[3 * faces[k] + 1];
            float4 u2 = g_fcol_pad[3 * faces[k] + 2];
            float t0 = b0 * u0.x + b1 * u1.x + b2 * u2.x;
            float t1 = b0 * u0.y + b1 * u1.y + b2 * u2.y;
            float t2 = b0 * u0.z + b1 * u1.z + b2 * u2.z;
            r += w * t0; g += w * t1; b += w * t2;
        }
    }

    float inv = __fdividef(1.0f, denom);
    float4 o;
    o.x = (r + delta) * inv;   // background = (1,1,1)
    o.y = (g + delta) * inv;
    o.z = (b + delta) * inv;
    o.w = keep;                // 1 - alpha
    out[p] = o;
}

extern "C" void kernel_launch(void* const* d_in, const int* in_sizes, int n_in,
                              void* d_out, int out_size) {
    const int*   p2f   = (const int*)d_in[0];
    const float* bary  = (const float*)d_in[1];
    const float* zbufp = (const float*)d_in[2];
    const float* dist  = (const float*)d_in[3];
    const float* fcol  = (const float*)d_in[4];
    int P = in_sizes[0] / 8;   // N*H*W pixels
    int F = in_sizes[4] / 9;   // faces

    pad_fcol_kernel<<<(F + 255) / 256, 256>>>(fcol, F);

    int threads = 256;
    int blocks  = (P + threads - 1) / threads;
    soft_shader_kernel<<<blocks, threads>>>(
        (const int4*)p2f, bary, (const float4*)zbufp, (const float4*)dist,
        (float4*)d_out, P);
}